// round 6
// baseline (speedup 1.0000x reference)
#include <cuda_runtime.h>

// Problem constants
#define BATCH 4
#define CIN   64
#define COUT  128
#define HH    512
#define WW    512
#define HWP   (HH*WW)          // 262144 pixels per (b,c) plane
#define NBLK  512
#define BSZ   32
#define PAD   34               // 32 + 2 zero-pad border
#define EPSF  1e-5f

// ---------------------------------------------------------------------------
// Scratch (zero-initialized at module load; borders of g_t1p are never written
// so SAME-conv zero padding holds across every graph replay).
// ---------------------------------------------------------------------------
__device__ float g_t1p[(size_t)NBLK * COUT * PAD * PAD];   // ~303 MB padded conv1 output
__device__ float g_t2 [(size_t)NBLK * COUT * BSZ * BSZ];   // ~268 MB conv2 output
__device__ float g_w1t[CIN  * COUT];                        // [c][o]
__device__ float g_w2t[9 * COUT * COUT];                    // [tap][c][o]
__device__ float g_w3t[COUT * COUT];                        // [c][o]
__device__ float g_wdt[CIN  * COUT];                        // [c][o]

// ---------------------------------------------------------------------------
// Weight transpose prep: make every GEMM A-tile load coalesced ([k][m] layout).
// ---------------------------------------------------------------------------
__global__ void prep_kernel(const float* __restrict__ w1, const float* __restrict__ w2,
                            const float* __restrict__ w3, const float* __restrict__ wd) {
    int t = blockIdx.x * blockDim.x + threadIdx.x;
    if (t < CIN * COUT) {
        int c = t / COUT, o = t % COUT;
        g_w1t[t] = w1[o * CIN + c];
        g_wdt[t] = wd[o * CIN + c];
    }
    if (t < COUT * COUT) {
        int c = t / COUT, o = t % COUT;
        g_w3t[t] = w3[o * COUT + c];
    }
    if (t < 9 * COUT * COUT) {
        int tap = t / (COUT * COUT);
        int r   = t % (COUT * COUT);
        int c = r / COUT, o = r % COUT;
        int di = tap / 3, dj = tap % 3;
        g_w2t[t] = w2[((o * COUT + c) * 3 + di) * 3 + dj];
    }
}

// ---------------------------------------------------------------------------
// Shared GEMM inner product: 16-deep K chunk, 8x8 register tile per thread.
// As/Bs: [16][128] flat. tx = tid&15 (pixel groups), ty = tid>>4 (chan groups).
// ---------------------------------------------------------------------------
#define GEMM_CHUNK(As, Bs, acc, tx, ty)                                        \
    do {                                                                       \
        _Pragma("unroll")                                                      \
        for (int k = 0; k < 16; k++) {                                         \
            float4 a0 = ((const float4*)(As))[k * 32 + (ty) * 2];              \
            float4 a1 = ((const float4*)(As))[k * 32 + (ty) * 2 + 1];          \
            float4 b0 = ((const float4*)(Bs))[k * 32 + (tx) * 2];              \
            float4 b1 = ((const float4*)(Bs))[k * 32 + (tx) * 2 + 1];          \
            float av[8] = {a0.x,a0.y,a0.z,a0.w,a1.x,a1.y,a1.z,a1.w};           \
            float bv[8] = {b0.x,b0.y,b0.z,b0.w,b1.x,b1.y,b1.z,b1.w};           \
            _Pragma("unroll")                                                  \
            for (int i = 0; i < 8; i++)                                        \
                _Pragma("unroll")                                              \
                for (int j = 0; j < 8; j++)                                    \
                    acc[i][j] = fmaf(av[i], bv[j], acc[i][j]);                 \
        }                                                                      \
    } while (0)

// ---------------------------------------------------------------------------
// Kernel 1: ybase = wd (1x1) over the full image + bd.  out = [4,128,512,512]
// One CTA = 128 out-channels x 128 contiguous pixels. 8192 CTAs.
// ---------------------------------------------------------------------------
__global__ __launch_bounds__(256)
void ybase_kernel(const float* __restrict__ x, const float* __restrict__ bd,
                  float* __restrict__ out) {
    __shared__ float As[2048], Bs[2048];
    int bid = blockIdx.x;
    int b  = bid >> 11;          // 2048 pixel tiles per image
    int p0 = (bid & 2047) * 128;
    const float* xb = x + (size_t)b * CIN * HWP + p0;
    int tid = threadIdx.x, tx = tid & 15, ty = tid >> 4;

    float acc[8][8];
#pragma unroll
    for (int i = 0; i < 8; i++)
#pragma unroll
        for (int j = 0; j < 8; j++) acc[i][j] = 0.f;

    for (int kc = 0; kc < CIN / 16; kc++) {
#pragma unroll
        for (int s = 0; s < 8; s++) {
            int e = tid + s * 256;
            As[e] = g_wdt[kc * 2048 + e];
            int k = e >> 7, p = e & 127;
            Bs[e] = xb[(size_t)(kc * 16 + k) * HWP + p];
        }
        __syncthreads();
        GEMM_CHUNK(As, Bs, acc, tx, ty);
        __syncthreads();
    }
#pragma unroll
    for (int i = 0; i < 8; i++) {
        int m = ty * 8 + i;
        float bias = bd[m];
        float* o = out + ((size_t)(b * COUT + m)) * HWP + p0 + tx * 8;
        float4 v0 = make_float4(acc[i][0]+bias, acc[i][1]+bias, acc[i][2]+bias, acc[i][3]+bias);
        float4 v1 = make_float4(acc[i][4]+bias, acc[i][5]+bias, acc[i][6]+bias, acc[i][7]+bias);
        ((float4*)o)[0] = v0;
        ((float4*)o)[1] = v1;
    }
}

// ---------------------------------------------------------------------------
// Kernel 2: gather + conv1(1x1) + BN + ReLU -> padded t1p interior.
// CTA = (block n, row-quad pt). 4096 CTAs.
// ---------------------------------------------------------------------------
__global__ __launch_bounds__(256)
void conv1_kernel(const float* __restrict__ x, const int* __restrict__ idx,
                  const float* __restrict__ b1, const float* __restrict__ g1,
                  const float* __restrict__ be1, const float* __restrict__ m1,
                  const float* __restrict__ v1) {
    __shared__ float As[2048], Bs[2048];
    int bid = blockIdx.x;
    int n = bid >> 3, pt = bid & 7;
    int rb = pt * 4;
    int b  = idx[n * 3], gh = idx[n * 3 + 1], gw = idx[n * 3 + 2];
    const float* xb = x + ((size_t)b * CIN * HH + (size_t)(gh * 32 + rb)) * WW + gw * 32;
    int tid = threadIdx.x, tx = tid & 15, ty = tid >> 4;

    float acc[8][8];
#pragma unroll
    for (int i = 0; i < 8; i++)
#pragma unroll
        for (int j = 0; j < 8; j++) acc[i][j] = 0.f;

    for (int kc = 0; kc < CIN / 16; kc++) {
#pragma unroll
        for (int s = 0; s < 8; s++) {
            int e = tid + s * 256;
            As[e] = g_w1t[kc * 2048 + e];
            int k = e >> 7, p = e & 127;
            int r = p >> 5, j = p & 31;
            Bs[e] = xb[(size_t)(kc * 16 + k) * HWP + r * WW + j];
        }
        __syncthreads();
        GEMM_CHUNK(As, Bs, acc, tx, ty);
        __syncthreads();
    }
    float* t1blk = g_t1p + (size_t)n * COUT * PAD * PAD;
#pragma unroll
    for (int i = 0; i < 8; i++) {
        int m = ty * 8 + i;
        float al = g1[m] * rsqrtf(v1[m] + EPSF);
        float bt = (b1[m] - m1[m]) * al + be1[m];
        int p0 = tx * 8;
        int r  = rb + (p0 >> 5) + 1;
        int j0 = (p0 & 31) + 1;
        float* dst = t1blk + (size_t)(m * PAD + r) * PAD + j0;
#pragma unroll
        for (int j = 0; j < 8; j++)
            dst[j] = fmaxf(fmaf(acc[i][j], al, bt), 0.f);
    }
}

// ---------------------------------------------------------------------------
// Kernel 3: conv2(3x3, SAME within block) + BN + ReLU -> t2.
// CTA = (block n, row-quad q). 9 tap-GEMMs x K=128 accumulated. 4096 CTAs.
// ---------------------------------------------------------------------------
__global__ __launch_bounds__(256)
void conv2_kernel(const float* __restrict__ b2, const float* __restrict__ g2,
                  const float* __restrict__ be2, const float* __restrict__ m2,
                  const float* __restrict__ v2) {
    __shared__ float As[2048], Bs[2048];
    int bid = blockIdx.x;
    int n = bid >> 3, q = bid & 7;
    int rb = q * 4;
    const float* t1blk = g_t1p + (size_t)n * COUT * PAD * PAD;
    int tid = threadIdx.x, tx = tid & 15, ty = tid >> 4;

    float acc[8][8];
#pragma unroll
    for (int i = 0; i < 8; i++)
#pragma unroll
        for (int j = 0; j < 8; j++) acc[i][j] = 0.f;

    for (int tap = 0; tap < 9; tap++) {
        int di = tap / 3, dj = tap % 3;
        const float* wt = g_w2t + tap * COUT * COUT;
        for (int kc = 0; kc < COUT / 16; kc++) {
#pragma unroll
            for (int s = 0; s < 8; s++) {
                int e = tid + s * 256;
                As[e] = wt[kc * 2048 + e];
                int k = e >> 7, p = e & 127;
                int rr = p >> 5, jj = p & 31;
                Bs[e] = t1blk[(size_t)((kc * 16 + k) * PAD + rb + rr + di) * PAD + dj + jj];
            }
            __syncthreads();
            GEMM_CHUNK(As, Bs, acc, tx, ty);
            __syncthreads();
        }
    }
    float* t2blk = g_t2 + (size_t)n * COUT * BSZ * BSZ;
#pragma unroll
    for (int i = 0; i < 8; i++) {
        int m = ty * 8 + i;
        float al = g2[m] * rsqrtf(v2[m] + EPSF);
        float bt = (b2[m] - m2[m]) * al + be2[m];
        float* dst = t2blk + (size_t)m * 1024 + rb * 32 + tx * 8;
        float4 v0 = make_float4(fmaxf(fmaf(acc[i][0],al,bt),0.f), fmaxf(fmaf(acc[i][1],al,bt),0.f),
                                fmaxf(fmaf(acc[i][2],al,bt),0.f), fmaxf(fmaf(acc[i][3],al,bt),0.f));
        float4 v1 = make_float4(fmaxf(fmaf(acc[i][4],al,bt),0.f), fmaxf(fmaf(acc[i][5],al,bt),0.f),
                                fmaxf(fmaf(acc[i][6],al,bt),0.f), fmaxf(fmaf(acc[i][7],al,bt),0.f));
        ((float4*)dst)[0] = v0;
        ((float4*)dst)[1] = v1;
    }
}

// ---------------------------------------------------------------------------
// Kernel 4: conv3(1x1) + BN + ReLU + scatter-add into out (blocks unique).
// 4096 CTAs.
// ---------------------------------------------------------------------------
__global__ __launch_bounds__(256)
void conv3_kernel(const int* __restrict__ idx,
                  const float* __restrict__ b3, const float* __restrict__ g3,
                  const float* __restrict__ be3, const float* __restrict__ m3,
                  const float* __restrict__ v3, float* __restrict__ out) {
    __shared__ float As[2048], Bs[2048];
    int bid = blockIdx.x;
    int n = bid >> 3, pt = bid & 7;
    int rb = pt * 4;
    int b  = idx[n * 3], gh = idx[n * 3 + 1], gw = idx[n * 3 + 2];
    const float* t2blk = g_t2 + (size_t)n * COUT * BSZ * BSZ;
    int tid = threadIdx.x, tx = tid & 15, ty = tid >> 4;

    float acc[8][8];
#pragma unroll
    for (int i = 0; i < 8; i++)
#pragma unroll
        for (int j = 0; j < 8; j++) acc[i][j] = 0.f;

    for (int kc = 0; kc < COUT / 16; kc++) {
#pragma unroll
        for (int s = 0; s < 8; s++) {
            int e = tid + s * 256;
            As[e] = g_w3t[kc * 2048 + e];
            int k = e >> 7, p = e & 127;
            Bs[e] = t2blk[(size_t)(kc * 16 + k) * 1024 + rb * 32 + p];
        }
        __syncthreads();
        GEMM_CHUNK(As, Bs, acc, tx, ty);
        __syncthreads();
    }
#pragma unroll
    for (int i = 0; i < 8; i++) {
        int m = ty * 8 + i;
        float al = g3[m] * rsqrtf(v3[m] + EPSF);
        float bt = (b3[m] - m3[m]) * al + be3[m];
        int p0 = tx * 8;
        int r  = gh * 32 + rb + (p0 >> 5);
        int j0 = gw * 32 + (p0 & 31);
        float* o = out + ((size_t)(b * COUT + m) * HH + r) * WW + j0;
        float4 o0 = ((float4*)o)[0];
        float4 o1 = ((float4*)o)[1];
        o0.x += fmaxf(fmaf(acc[i][0],al,bt),0.f); o0.y += fmaxf(fmaf(acc[i][1],al,bt),0.f);
        o0.z += fmaxf(fmaf(acc[i][2],al,bt),0.f); o0.w += fmaxf(fmaf(acc[i][3],al,bt),0.f);
        o1.x += fmaxf(fmaf(acc[i][4],al,bt),0.f); o1.y += fmaxf(fmaf(acc[i][5],al,bt),0.f);
        o1.z += fmaxf(fmaf(acc[i][6],al,bt),0.f); o1.w += fmaxf(fmaf(acc[i][7],al,bt),0.f);
        ((float4*)o)[0] = o0;
        ((float4*)o)[1] = o1;
    }
}

// ---------------------------------------------------------------------------
extern "C" void kernel_launch(void* const* d_in, const int* in_sizes, int n_in,
                              void* d_out, int out_size) {
    (void)in_sizes; (void)n_in; (void)out_size;
    const float* x   = (const float*)d_in[0];
    const int*   idx = (const int*)  d_in[1];
    const float* w1  = (const float*)d_in[2];
    const float* b1  = (const float*)d_in[3];
    const float* w2  = (const float*)d_in[4];
    const float* b2  = (const float*)d_in[5];
    const float* w3  = (const float*)d_in[6];
    const float* b3  = (const float*)d_in[7];
    const float* wd  = (const float*)d_in[8];
    const float* bd  = (const float*)d_in[9];
    const float* g1  = (const float*)d_in[10];
    const float* be1 = (const float*)d_in[11];
    const float* m1  = (const float*)d_in[12];
    const float* v1  = (const float*)d_in[13];
    const float* g2  = (const float*)d_in[14];
    const float* be2 = (const float*)d_in[15];
    const float* m2  = (const float*)d_in[16];
    const float* v2  = (const float*)d_in[17];
    const float* g3  = (const float*)d_in[18];
    const float* be3 = (const float*)d_in[19];
    const float* m3  = (const float*)d_in[20];
    const float* v3  = (const float*)d_in[21];
    float* out = (float*)d_out;

    prep_kernel<<<(9 * COUT * COUT + 255) / 256, 256>>>(w1, w2, w3, wd);
    ybase_kernel<<<BATCH * 2048, 256>>>(x, bd, out);
    conv1_kernel<<<NBLK * 8, 256>>>(x, idx, b1, g1, be1, m1, v1);
    conv2_kernel<<<NBLK * 8, 256>>>(b2, g2, be2, m2, v2);
    conv3_kernel<<<NBLK * 8, 256>>>(idx, b3, g3, be3, m3, v3, out);
}

// round 11
// speedup vs baseline: 1.6652x; 1.6652x over previous
#include <cuda_runtime.h>
#include <cuda_bf16.h>
#include <cstdint>

// Problem constants
#define BATCH 4
#define CIN   64
#define COUT  128
#define HH    512
#define WW    512
#define HWP   (HH*WW)
#define NBLK  512
#define BSZ   32
#define PAD   34               // 32 + 2 zero-pad border
#define PPX   (PAD*PAD)        // 1156 padded pixels per block
#define EPSF  1e-5f

// ---------------------------------------------------------------------------
// Scratch (zero-init at module load). Borders of padded t1 planes never
// written -> SAME-conv zero padding holds across graph replays.
// ---------------------------------------------------------------------------
__device__ __nv_bfloat16 g_t1hi[(size_t)NBLK * PPX * COUT];   // [n][px34x34][ch]
__device__ __nv_bfloat16 g_t1lo[(size_t)NBLK * PPX * COUT];   // residual plane
__device__ float g_t2 [(size_t)NBLK * COUT * BSZ * BSZ];      // conv2 out [n][ch][px]
__device__ float g_w1t[CIN  * COUT];                          // [c][o]
__device__ float g_w3t[COUT * COUT];                          // [c][o]
__device__ float g_wdt[CIN  * COUT];                          // [c][o]
__device__ __nv_bfloat16 g_w2h[9 * COUT * COUT];              // [tap][o][c] hi
__device__ __nv_bfloat16 g_w2l[9 * COUT * COUT];              // [tap][o][c] lo

__device__ __forceinline__ uint32_t smem_u32(const void* p) {
    uint32_t a;
    asm("{ .reg .u64 t; cvta.to.shared.u64 t, %1; cvt.u32.u64 %0, t; }" : "=r"(a) : "l"(p));
    return a;
}
#define SWZ128(off) ((off) ^ (((off) >> 3) & 0x70))

// mma.sync m16n8k16 bf16 (baseline PTX, sm_80+; HMMA on sm_103)
__device__ __forceinline__ void mma16816(float* d, const uint32_t* a, const uint32_t* b) {
    asm volatile(
        "mma.sync.aligned.m16n8k16.row.col.f32.bf16.bf16.f32 "
        "{%0,%1,%2,%3}, {%4,%5,%6,%7}, {%8,%9}, {%0,%1,%2,%3};"
        : "+f"(d[0]), "+f"(d[1]), "+f"(d[2]), "+f"(d[3])
        : "r"(a[0]), "r"(a[1]), "r"(a[2]), "r"(a[3]), "r"(b[0]), "r"(b[1]));
}
__device__ __forceinline__ void ldsm_x4(uint32_t* r, uint32_t addr) {
    asm volatile("ldmatrix.sync.aligned.m8n8.x4.shared.b16 {%0,%1,%2,%3}, [%4];"
        : "=r"(r[0]), "=r"(r[1]), "=r"(r[2]), "=r"(r[3]) : "r"(addr));
}

// ---------------------------------------------------------------------------
// Weight prep: fp32 transposes + bf16 hi/lo split of w2 into [tap][o][c].
// ---------------------------------------------------------------------------
__global__ void prep_kernel(const float* __restrict__ w1, const float* __restrict__ w2,
                            const float* __restrict__ w3, const float* __restrict__ wd) {
    int t = blockIdx.x * blockDim.x + threadIdx.x;
    if (t < CIN * COUT) {
        int c = t / COUT, o = t % COUT;
        g_w1t[t] = w1[o * CIN + c];
        g_wdt[t] = wd[o * CIN + c];
    }
    if (t < COUT * COUT) {
        int c = t / COUT, o = t % COUT;
        g_w3t[t] = w3[o * COUT + c];
    }
    if (t < 9 * COUT * COUT) {
        int tap = t / (COUT * COUT);
        int r   = t % (COUT * COUT);
        int o = r / COUT, c = r % COUT;
        int di = tap / 3, dj = tap % 3;
        float w = w2[((o * COUT + c) * 3 + di) * 3 + dj];
        __nv_bfloat16 hi = __float2bfloat16(w);
        g_w2h[t] = hi;
        g_w2l[t] = __float2bfloat16(w - __bfloat162float(hi));
    }
}

// ---------------------------------------------------------------------------
// Shared FFMA GEMM inner product (ybase / conv1 / conv3)
// ---------------------------------------------------------------------------
#define GEMM_CHUNK(As, Bs, acc, tx, ty)                                        \
    do {                                                                       \
        _Pragma("unroll")                                                      \
        for (int k = 0; k < 16; k++) {                                         \
            float4 a0 = ((const float4*)(As))[k * 32 + (ty) * 2];              \
            float4 a1 = ((const float4*)(As))[k * 32 + (ty) * 2 + 1];          \
            float4 b0 = ((const float4*)(Bs))[k * 32 + (tx) * 2];              \
            float4 b1 = ((const float4*)(Bs))[k * 32 + (tx) * 2 + 1];          \
            float av[8] = {a0.x,a0.y,a0.z,a0.w,a1.x,a1.y,a1.z,a1.w};           \
            float bv[8] = {b0.x,b0.y,b0.z,b0.w,b1.x,b1.y,b1.z,b1.w};           \
            _Pragma("unroll")                                                  \
            for (int i = 0; i < 8; i++)                                        \
                _Pragma("unroll")                                              \
                for (int j = 0; j < 8; j++)                                    \
                    acc[i][j] = fmaf(av[i], bv[j], acc[i][j]);                 \
        }                                                                      \
    } while (0)

// ---------------------------------------------------------------------------
// Kernel 1: ybase = wd (1x1) over full image + bd. 8192 CTAs.
// ---------------------------------------------------------------------------
__global__ __launch_bounds__(256)
void ybase_kernel(const float* __restrict__ x, const float* __restrict__ bd,
                  float* __restrict__ out) {
    __shared__ float As[2048], Bs[2048];
    int bid = blockIdx.x;
    int b  = bid >> 11;
    int p0 = (bid & 2047) * 128;
    const float* xb = x + (size_t)b * CIN * HWP + p0;
    int tid = threadIdx.x, tx = tid & 15, ty = tid >> 4;

    float acc[8][8];
#pragma unroll
    for (int i = 0; i < 8; i++)
#pragma unroll
        for (int j = 0; j < 8; j++) acc[i][j] = 0.f;

    for (int kc = 0; kc < CIN / 16; kc++) {
#pragma unroll
        for (int s = 0; s < 8; s++) {
            int e = tid + s * 256;
            As[e] = g_wdt[kc * 2048 + e];
            int k = e >> 7, p = e & 127;
            Bs[e] = xb[(size_t)(kc * 16 + k) * HWP + p];
        }
        __syncthreads();
        GEMM_CHUNK(As, Bs, acc, tx, ty);
        __syncthreads();
    }
#pragma unroll
    for (int i = 0; i < 8; i++) {
        int m = ty * 8 + i;
        float bias = bd[m];
        float* o = out + ((size_t)(b * COUT + m)) * HWP + p0 + tx * 8;
        ((float4*)o)[0] = make_float4(acc[i][0]+bias, acc[i][1]+bias, acc[i][2]+bias, acc[i][3]+bias);
        ((float4*)o)[1] = make_float4(acc[i][4]+bias, acc[i][5]+bias, acc[i][6]+bias, acc[i][7]+bias);
    }
}

// ---------------------------------------------------------------------------
// Kernel 2: gather + conv1(1x1) + BN + ReLU -> t1 bf16 hi/lo planes,
// [px-padded][ch] layout (MMA B-operand ready). 4096 CTAs.
// ---------------------------------------------------------------------------
__global__ __launch_bounds__(256)
void conv1_kernel(const float* __restrict__ x, const int* __restrict__ idx,
                  const float* __restrict__ b1, const float* __restrict__ g1,
                  const float* __restrict__ be1, const float* __restrict__ m1,
                  const float* __restrict__ v1) {
    __shared__ float As[2048], Bs[2048];
    int bid = blockIdx.x;
    int n = bid >> 3, pt = bid & 7;
    int rb = pt * 4;
    int b  = idx[n * 3], gh = idx[n * 3 + 1], gw = idx[n * 3 + 2];
    const float* xb = x + ((size_t)b * CIN * HH + (size_t)(gh * 32 + rb)) * WW + gw * 32;
    int tid = threadIdx.x, tx = tid & 15, ty = tid >> 4;

    float acc[8][8];
#pragma unroll
    for (int i = 0; i < 8; i++)
#pragma unroll
        for (int j = 0; j < 8; j++) acc[i][j] = 0.f;

    for (int kc = 0; kc < CIN / 16; kc++) {
#pragma unroll
        for (int s = 0; s < 8; s++) {
            int e = tid + s * 256;
            As[e] = g_w1t[kc * 2048 + e];
            int k = e >> 7, p = e & 127;
            int r = p >> 5, j = p & 31;
            Bs[e] = xb[(size_t)(kc * 16 + k) * HWP + r * WW + j];
        }
        __syncthreads();
        GEMM_CHUNK(As, Bs, acc, tx, ty);
        __syncthreads();
    }

    __nv_bfloat16* dhi = g_t1hi + (size_t)n * PPX * COUT;
    __nv_bfloat16* dlo = g_t1lo + (size_t)n * PPX * COUT;
    float al[8], bt[8];
#pragma unroll
    for (int i = 0; i < 8; i++) {
        int m = ty * 8 + i;
        al[i] = g1[m] * rsqrtf(v1[m] + EPSF);
        bt[i] = (b1[m] - m1[m]) * al[i] + be1[m];
    }
    int p0 = tx * 8;
    int prow  = rb + (p0 >> 5) + 1;
    int pcol0 = (p0 & 31) + 1;
#pragma unroll
    for (int j = 0; j < 8; j++) {
        int p = prow * PAD + pcol0 + j;
        __align__(16) __nv_bfloat16 h8[8], l8[8];
#pragma unroll
        for (int i = 0; i < 8; i++) {
            float v = fmaxf(fmaf(acc[i][j], al[i], bt[i]), 0.f);
            __nv_bfloat16 h = __float2bfloat16(v);
            h8[i] = h;
            l8[i] = __float2bfloat16(v - __bfloat162float(h));
        }
        *(uint4*)(dhi + (size_t)p * COUT + ty * 8) = *(const uint4*)h8;
        *(uint4*)(dlo + (size_t)p * COUT + ty * 8) = *(const uint4*)l8;
    }
}

// ---------------------------------------------------------------------------
// Kernel 3: conv2 via mma.sync bf16 split-precision (3-term) HMMA.
// CTA = (block n, 4-row quad q): D[128 out-ch][128 px], K = 9 taps x 128 ch.
// Warp grid 2(M)x4(N); warp tile 64x32; acc[4][4][4] f32 in registers.
// smem per K64-chunk: Ah/Al/Bh/Bl tiles [128 rows][64 bf16] SW128. 4096 CTAs.
// ---------------------------------------------------------------------------
#define C2_TILE  16384
#define C2_SMEM  (4 * C2_TILE)   // 64 KB dynamic

__global__ __launch_bounds__(256)
void conv2_mma_kernel(const float* __restrict__ b2, const float* __restrict__ g2,
                      const float* __restrict__ be2, const float* __restrict__ m2,
                      const float* __restrict__ v2) {
    extern __shared__ __align__(1024) char smem[];
    char* sAh = smem;
    char* sAl = smem + C2_TILE;
    char* sBh = smem + 2 * C2_TILE;
    char* sBl = smem + 3 * C2_TILE;
    __shared__ float s_al[COUT], s_bt[COUT];

    int tid = threadIdx.x, wid = tid >> 5, lane = tid & 31;
    int bid = blockIdx.x;
    int n = bid >> 3, q = bid & 7;
    int r0 = q * 4;
    int wm = wid & 1, wn = wid >> 1;        // warp tile: M 64, N 32
    int lr = lane >> 2, lc = lane & 3;       // fragment row group / col pair

    if (tid < COUT) {
        float a = g2[tid] * rsqrtf(v2[tid] + EPSF);
        s_al[tid] = a;
        s_bt[tid] = (b2[tid] - m2[tid]) * a + be2[tid];
    }

    const __nv_bfloat16* t1h = g_t1hi + (size_t)n * PPX * COUT;
    const __nv_bfloat16* t1l = g_t1lo + (size_t)n * PPX * COUT;
    uint32_t uAh = smem_u32(sAh), uAl = smem_u32(sAl);

    float acc[4][4][4];
#pragma unroll
    for (int mi = 0; mi < 4; mi++)
#pragma unroll
        for (int ni = 0; ni < 4; ni++)
#pragma unroll
            for (int c = 0; c < 4; c++) acc[mi][ni][c] = 0.f;

    // A-frag ldmatrix address pattern (within tile): row = lane&15, kcol group
    int a_row_in = lane & 15;
    int a_kb16   = (lane >> 4) * 16;        // +16B for k+8 half

    for (int tap = 0; tap < 9; tap++) {
        int di = tap / 3, dj = tap % 3;
        const __nv_bfloat16* wh = g_w2h + (size_t)tap * COUT * COUT;
        const __nv_bfloat16* wl = g_w2l + (size_t)tap * COUT * COUT;
        for (int kc = 0; kc < 2; kc++) {
            // Fill 4 tiles: [128 rows][64 bf16], SW128, 16B per thread-step.
#pragma unroll
            for (int s = 0; s < 4; s++) {
                int v = tid + s * 256;
                int row = v >> 3, u = v & 7;
                uint32_t sw = SWZ128((uint32_t)(row * 128 + u * 16));
                size_t wof = (size_t)row * COUT + kc * 64 + u * 8;
                *(uint4*)(sAh + sw) = *(const uint4*)(wh + wof);
                *(uint4*)(sAl + sw) = *(const uint4*)(wl + wof);
                int rr = row >> 5, jj = row & 31;
                int p = (r0 + rr + di) * PAD + jj + dj;
                size_t tof = (size_t)p * COUT + kc * 64 + u * 8;
                *(uint4*)(sBh + sw) = *(const uint4*)(t1h + tof);
                *(uint4*)(sBl + sw) = *(const uint4*)(t1l + tof);
            }
            __syncthreads();

#pragma unroll
            for (int ks = 0; ks < 4; ks++) {
                int k0b = ks * 32;   // k16 step in bytes (16 bf16)
                uint32_t ah[4][4], al4[4][4];
#pragma unroll
                for (int mi = 0; mi < 4; mi++) {
                    int mrow = wm * 64 + mi * 16 + a_row_in;
                    uint32_t off = SWZ128((uint32_t)(mrow * 128 + k0b + a_kb16));
                    ldsm_x4(ah[mi],  uAh + off);
                    ldsm_x4(al4[mi], uAl + off);
                }
                uint32_t bh[4][2], bl[4][2];
#pragma unroll
                for (int ni = 0; ni < 4; ni++) {
                    int nrow = wn * 32 + ni * 8 + lr;
                    uint32_t base = (uint32_t)(nrow * 128 + k0b + lc * 4);
                    bh[ni][0] = *(const uint32_t*)(sBh + SWZ128(base));
                    bh[ni][1] = *(const uint32_t*)(sBh + SWZ128(base + 16));
                    bl[ni][0] = *(const uint32_t*)(sBl + SWZ128(base));
                    bl[ni][1] = *(const uint32_t*)(sBl + SWZ128(base + 16));
                }
#pragma unroll
                for (int mi = 0; mi < 4; mi++)
#pragma unroll
                    for (int ni = 0; ni < 4; ni++) {
                        mma16816(acc[mi][ni], ah[mi],  bh[ni]);
                        mma16816(acc[mi][ni], ah[mi],  bl[ni]);
                        mma16816(acc[mi][ni], al4[mi], bh[ni]);
                    }
            }
            __syncthreads();
        }
    }

    // Epilogue: BN + ReLU, write t2 [n][ch][1024] at pixel offset q*128.
#pragma unroll
    for (int mi = 0; mi < 4; mi++) {
        int m0 = wm * 64 + mi * 16 + lr;
        int m1r = m0 + 8;
        float a0 = s_al[m0], c0 = s_bt[m0];
        float a1 = s_al[m1r], c1 = s_bt[m1r];
        float* d0 = g_t2 + ((size_t)n * COUT + m0)  * 1024 + q * 128;
        float* d1 = g_t2 + ((size_t)n * COUT + m1r) * 1024 + q * 128;
#pragma unroll
        for (int ni = 0; ni < 4; ni++) {
            int npx = wn * 32 + ni * 8 + lc * 2;
            float2 v0, v1;
            v0.x = fmaxf(fmaf(acc[mi][ni][0], a0, c0), 0.f);
            v0.y = fmaxf(fmaf(acc[mi][ni][1], a0, c0), 0.f);
            v1.x = fmaxf(fmaf(acc[mi][ni][2], a1, c1), 0.f);
            v1.y = fmaxf(fmaf(acc[mi][ni][3], a1, c1), 0.f);
            *(float2*)(d0 + npx) = v0;
            *(float2*)(d1 + npx) = v1;
        }
    }
}

// ---------------------------------------------------------------------------
// Kernel 4: conv3(1x1) + BN + ReLU + scatter-add (blocks unique). 4096 CTAs.
// ---------------------------------------------------------------------------
__global__ __launch_bounds__(256)
void conv3_kernel(const int* __restrict__ idx,
                  const float* __restrict__ b3, const float* __restrict__ g3,
                  const float* __restrict__ be3, const float* __restrict__ m3,
                  const float* __restrict__ v3, float* __restrict__ out) {
    __shared__ float As[2048], Bs[2048];
    int bid = blockIdx.x;
    int n = bid >> 3, pt = bid & 7;
    int rb = pt * 4;
    int b  = idx[n * 3], gh = idx[n * 3 + 1], gw = idx[n * 3 + 2];
    const float* t2blk = g_t2 + (size_t)n * COUT * BSZ * BSZ;
    int tid = threadIdx.x, tx = tid & 15, ty = tid >> 4;

    float acc[8][8];
#pragma unroll
    for (int i = 0; i < 8; i++)
#pragma unroll
        for (int j = 0; j < 8; j++) acc[i][j] = 0.f;

    for (int kc = 0; kc < COUT / 16; kc++) {
#pragma unroll
        for (int s = 0; s < 8; s++) {
            int e = tid + s * 256;
            As[e] = g_w3t[kc * 2048 + e];
            int k = e >> 7, p = e & 127;
            Bs[e] = t2blk[(size_t)(kc * 16 + k) * 1024 + rb * 32 + p];
        }
        __syncthreads();
        GEMM_CHUNK(As, Bs, acc, tx, ty);
        __syncthreads();
    }
#pragma unroll
    for (int i = 0; i < 8; i++) {
        int m = ty * 8 + i;
        float al = g3[m] * rsqrtf(v3[m] + EPSF);
        float bt = (b3[m] - m3[m]) * al + be3[m];
        int p0 = tx * 8;
        int r  = gh * 32 + rb + (p0 >> 5);
        int j0 = gw * 32 + (p0 & 31);
        float* o = out + ((size_t)(b * COUT + m) * HH + r) * WW + j0;
        float4 o0 = ((float4*)o)[0];
        float4 o1 = ((float4*)o)[1];
        o0.x += fmaxf(fmaf(acc[i][0],al,bt),0.f); o0.y += fmaxf(fmaf(acc[i][1],al,bt),0.f);
        o0.z += fmaxf(fmaf(acc[i][2],al,bt),0.f); o0.w += fmaxf(fmaf(acc[i][3],al,bt),0.f);
        o1.x += fmaxf(fmaf(acc[i][4],al,bt),0.f); o1.y += fmaxf(fmaf(acc[i][5],al,bt),0.f);
        o1.z += fmaxf(fmaf(acc[i][6],al,bt),0.f); o1.w += fmaxf(fmaf(acc[i][7],al,bt),0.f);
        ((float4*)o)[0] = o0;
        ((float4*)o)[1] = o1;
    }
}

// ---------------------------------------------------------------------------
extern "C" void kernel_launch(void* const* d_in, const int* in_sizes, int n_in,
                              void* d_out, int out_size) {
    (void)in_sizes; (void)n_in; (void)out_size;
    const float* x   = (const float*)d_in[0];
    const int*   idx = (const int*)  d_in[1];
    const float* w1  = (const float*)d_in[2];
    const float* b1  = (const float*)d_in[3];
    const float* w2  = (const float*)d_in[4];
    const float* b2  = (const float*)d_in[5];
    const float* w3  = (const float*)d_in[6];
    const float* b3  = (const float*)d_in[7];
    const float* wd  = (const float*)d_in[8];
    const float* bd  = (const float*)d_in[9];
    const float* g1  = (const float*)d_in[10];
    const float* be1 = (const float*)d_in[11];
    const float* m1  = (const float*)d_in[12];
    const float* v1  = (const float*)d_in[13];
    const float* g2  = (const float*)d_in[14];
    const float* be2 = (const float*)d_in[15];
    const float* m2  = (const float*)d_in[16];
    const float* v2  = (const float*)d_in[17];
    const float* g3  = (const float*)d_in[18];
    const float* be3 = (const float*)d_in[19];
    const float* m3  = (const float*)d_in[20];
    const float* v3  = (const float*)d_in[21];
    float* out = (float*)d_out;

    static int smem_set = 0;
    if (!smem_set) {
        cudaFuncSetAttribute(conv2_mma_kernel,
                             cudaFuncAttributeMaxDynamicSharedMemorySize, C2_SMEM);
        smem_set = 1;
    }

    prep_kernel<<<(9 * COUT * COUT + 255) / 256, 256>>>(w1, w2, w3, wd);
    ybase_kernel<<<BATCH * 2048, 256>>>(x, bd, out);
    conv1_kernel<<<NBLK * 8, 256>>>(x, idx, b1, g1, be1, m1, v1);
    conv2_mma_kernel<<<NBLK * 8, 256, C2_SMEM>>>(b2, g2, be2, m2, v2);
    conv3_kernel<<<NBLK * 8, 256>>>(idx, b3, g3, be3, m3, v3, out);
}